// round 14
// baseline (speedup 1.0000x reference)
#include <cuda_runtime.h>
#include <cuda_fp16.h>
#include <cstdint>

#define HIDDEN   512
#define LATENT   128
#define NTOT     768          // 128 (mu) + 512 (u) + 128 (d)
#define MROWS    128          // rows per CTA
#define THREADS  512          // 16 warps: 8 m-groups x 2 n-halves
#define KTILE    64
#define XSTRIDE  520          // 512 + 8 fp16 -> conflict-free ldmatrix
#define WSTRIDE  72           // 64 + 8 fp16  -> conflict-free ldmatrix
#define WS_ELEMS (128 * WSTRIDE)       // per stage
#define RSTRIDE  132
#define NSTATS   16
#define NSTAGES  48           // 6 chunks x 8 k-tiles
#define NRING    3

// W fused+transposed fp16, layout [n=768][k=512]: n = [mu 0-127 | u 128-639 | d 640-767]
__device__ __half g_Wt[(size_t)NTOT * HIDDEN];
__device__ double g_sum;
__device__ unsigned g_done;

// Coalesced transpose: 32k x 64n fp32 tile -> [n][k] fp16, via padded smem.
// grid.x = 192 tiles: tile t -> n0 = (t % 12) * 64, k0 = (t / 12) * 32
__global__ void convertW_kernel(const float* __restrict__ W_mu,
                                const float* __restrict__ W_u,
                                const float* __restrict__ W_d) {
    __shared__ float tile_s[32][65];
    const int t  = blockIdx.x;
    const int n0 = (t % 12) * 64;
    const int k0 = (t / 12) * 32;
    if (threadIdx.x == 0 && t == 0) { g_sum = 0.0; g_done = 0u; }

    const float* src; int ld, nloc;
    if (n0 < 128)      { src = W_mu; ld = 128; nloc = n0; }
    else if (n0 < 640) { src = W_u;  ld = 512; nloc = n0 - 128; }
    else               { src = W_d;  ld = 128; nloc = n0 - 640; }

    const int tx = threadIdx.x & 63;
    const int ty = threadIdx.x >> 6;          // 0..3
    #pragma unroll
    for (int i = 0; i < 8; i++) {
        int k = ty + i * 4;
        tile_s[k][tx] = src[(size_t)(k0 + k) * ld + nloc + tx];     // coalesced 64-wide
    }
    __syncthreads();
    const int tx2 = threadIdx.x & 31;
    const int ty2 = threadIdx.x >> 5;          // 0..7
    #pragma unroll
    for (int i = 0; i < 8; i++) {
        int n = ty2 + i * 8;
        g_Wt[(size_t)(n0 + n) * HIDDEN + k0 + tx2] =
            __float2half_rn(tile_s[tx2][n]);                         // coalesced fp16 writes
    }
}

__device__ __forceinline__ unsigned smem_u32(const void* p) {
    return (unsigned)__cvta_generic_to_shared(p);
}
__device__ __forceinline__ void ldsm4(unsigned& r0, unsigned& r1, unsigned& r2, unsigned& r3, unsigned a) {
    asm volatile("ldmatrix.sync.aligned.m8n8.x4.shared.b16 {%0,%1,%2,%3}, [%4];"
                 : "=r"(r0), "=r"(r1), "=r"(r2), "=r"(r3) : "r"(a));
}
// fp16-accumulate HMMA: c0 = row g cols(2q,2q+1), c1 = row g+8
__device__ __forceinline__ void mma16816h(unsigned& c0, unsigned& c1,
                                          unsigned a0, unsigned a1, unsigned a2, unsigned a3,
                                          unsigned b0, unsigned b1) {
    asm volatile("mma.sync.aligned.m16n8k16.row.col.f16.f16.f16.f16 "
                 "{%0,%1},{%2,%3,%4,%5},{%6,%7},{%0,%1};"
                 : "+r"(c0), "+r"(c1)
                 : "r"(a0), "r"(a1), "r"(a2), "r"(a3), "r"(b0), "r"(b1));
}
__device__ __forceinline__ void cpasync16(unsigned dst, const void* src) {
    asm volatile("cp.async.cg.shared.global [%0], [%1], 16;" :: "r"(dst), "l"(src) : "memory");
}
#define CP_COMMIT() asm volatile("cp.async.commit_group;" ::: "memory")
#define CP_WAIT(n)  asm volatile("cp.async.wait_group %0;" :: "n"(n) : "memory")

extern __shared__ char smem_raw[];

__global__ void __launch_bounds__(THREADS, 1)
lrg_main(const float* __restrict__ x,
         const float* __restrict__ b_mu,
         const float* __restrict__ b_u,
         const float* __restrict__ b_d,
         float* __restrict__ out, int Ntot)
{
    // ---- shared memory layout (230,400 B dynamic) ----
    __half* xs = (__half*)smem_raw;                            // [128][XSTRIDE]      133,120 B
    __half* ws = xs + MROWS * XSTRIDE;                         // 3 x [128][WSTRIDE]   55,296 B
    __half* rs = ws + NRING * WS_ELEMS;                        // [128][RSTRIDE]       33,792 B
    float* stats = (float*)(rs + 128 * RSTRIDE);               // [128][NSTATS]         8,192 B

    const int tid  = threadIdx.x;
    const int wid  = tid >> 5;
    const int lane = tid & 31;
    const int mw   = wid & 7;          // M group: 16 rows
    const int nh   = wid >> 3;         // N half: 64 cols
    const int q    = lane & 3;
    const int g    = lane >> 2;
    const int r0   = mw * 16 + g;
    const int r1   = r0 + 8;
    const int rowbase = blockIdx.x * MROWS;

    for (int i = tid; i < 128 * NSTATS; i += THREADS) stats[i] = 0.f;

    const unsigned xs_base = smem_u32(xs);
    const unsigned ws_base = smem_u32(ws);
    const float4* xg = (const float4*)(x + (size_t)rowbase * HIDDEN);

    // chunk order: mu, d, u0..u3 (d before u so rsqrt(d) ready)
    const int nb_tab[6] = {0, 640, 128, 256, 384, 512};

    // cp.async producer for one stage: W tile [128n][64k] -> ring slot
    auto issue_stage = [&](int s) {
        const int slot = s % NRING;
        const int nb = nb_tab[s >> 3];
        const int kt = s & 7;
        const __half* srcb = g_Wt + (size_t)nb * HIDDEN + kt * KTILE;
        const unsigned dbase = ws_base + (unsigned)(slot * WS_ELEMS * 2);
        #pragma unroll
        for (int c = tid; c < 1024; c += THREADS) {      // 2 iters x 16B
            int n  = c >> 3;
            int k8 = c & 7;
            cpasync16(dbase + (unsigned)(n * (WSTRIDE * 2) + k8 * 16),
                      srcb + (size_t)n * HIDDEN + k8 * 8);
        }
        CP_COMMIT();
    };

    // x k-tile loader: tile xt covers cols [xt*64, xt*64+64); 4 float4 per thread
    auto load_x_tile = [&](int xt) {
        #pragma unroll
        for (int j = 0; j < 4; j++) {
            int idx = tid + j * THREADS;        // 2048 float4 per tile
            int row = idx >> 4;                 // 16 float4 per row-tile
            int c4  = idx & 15;
            float4 v = xg[row * 128 + xt * 16 + c4];
            __half2* dst = (__half2*)(xs + row * XSTRIDE + xt * 64 + c4 * 4);
            dst[0] = __floats2half2_rn(v.x, v.y);
            dst[1] = __floats2half2_rn(v.z, v.w);
        }
    };

    // W stages 0,1 in flight, then ONLY x tile 0 (rest staged inside chunk 0)
    issue_stage(0);
    issue_stage(1);
    load_x_tile(0);
    CP_WAIT(1);
    __syncthreads();

    // ---- ldmatrix per-lane addressing ----
    const int t8 = lane >> 3;
    const int ri = lane & 7;
    // A: rows mw*16 + (t8&1)*8 + ri, k + ((t8>>1)&1)*8
    const unsigned a_addr0 = xs_base +
        (unsigned)(((mw * 16 + ((t8 & 1) << 3) + ri) * XSTRIDE + (((t8 >> 1) & 1) << 3)) * 2);
    // B: n = nh*64 + p*16 + ((t8>>1)&1)*8 + ri, k + (t8&1)*8
    const unsigned b_addr0 = ws_base +
        (unsigned)(((nh * 64 + (((t8 >> 1) & 1) << 3) + ri) * WSTRIDE + ((t8 & 1) << 3)) * 2);

    unsigned acc[8][2];

    #pragma unroll 1
    for (int s = 0; s < NSTAGES; s++) {
        const int slot = s % NRING;
        const int ch = s >> 3;
        const int kt = s & 7;

        if (kt == 0) {
            #pragma unroll
            for (int i = 0; i < 8; i++) { acc[i][0] = 0u; acc[i][1] = 0u; }
        }

        const unsigned b_st = b_addr0 + (unsigned)(slot * WS_ELEMS * 2);
        const int k0 = kt * KTILE;
        #pragma unroll
        for (int ks = 0; ks < 4; ks++) {
            unsigned a0, a1, a2, a3;
            ldsm4(a0, a1, a2, a3, a_addr0 + (unsigned)((k0 + ks * 16) * 2));
            #pragma unroll
            for (int p = 0; p < 4; p++) {
                unsigned b0, b1, b2, b3;
                ldsm4(b0, b1, b2, b3,
                      b_st + (unsigned)(p * 16 * WSTRIDE * 2 + ks * 16 * 2));
                mma16816h(acc[2 * p][0],     acc[2 * p][1],     a0, a1, a2, a3, b0, b1);
                mma16816h(acc[2 * p + 1][0], acc[2 * p + 1][1], a0, a1, a2, a3, b2, b3);
            }
        }

        // issue next+1 W stage into the slot stage s-1 used
        if (s + 2 < NSTAGES) issue_stage(s + 2);
        // progressive x staging: during chunk-0 stage kt, fetch x tile kt+1
        if (s < 7) load_x_tile(s + 1);

        if (kt == 7) {
            // ================= fused epilogue for chunk ch =================
            // lane owns cols ncol = nh*64 + ni*8 + q*2 + {0,1}; rows r0 (reg0), r1 (reg1)
            if (ch == 0) {
                float s0 = 0.f, s1 = 0.f;
                #pragma unroll
                for (int ni = 0; ni < 8; ni++) {
                    int ncol = nh * 64 + ni * 8 + q * 2;
                    float bv0 = __ldg(b_mu + ncol), bv1 = __ldg(b_mu + ncol + 1);
                    float2 f0 = __half22float2(*(__half2*)&acc[ni][0]);
                    float2 f1 = __half22float2(*(__half2*)&acc[ni][1]);
                    float v0 = f0.x + bv0, v1 = f0.y + bv1;
                    float v2 = f1.x + bv0, v3 = f1.y + bv1;
                    s0 += v0 * v0 + v1 * v1;
                    s1 += v2 * v2 + v3 * v3;
                }
                s0 += __shfl_xor_sync(~0u, s0, 1); s0 += __shfl_xor_sync(~0u, s0, 2);
                s1 += __shfl_xor_sync(~0u, s1, 1); s1 += __shfl_xor_sync(~0u, s1, 2);
                if (q == 0) {
                    atomicAdd(&stats[r0 * NSTATS + 0], s0);
                    atomicAdd(&stats[r1 * NSTATS + 0], s1);
                }
            } else if (ch == 1) {
                float sd0 = 0.f, sd1 = 0.f, sz0 = 0.f, sz1 = 0.f;
                #pragma unroll
                for (int ni = 0; ni < 8; ni++) {
                    int ncol = nh * 64 + ni * 8 + q * 2;
                    float bv0 = __ldg(b_d + ncol), bv1 = __ldg(b_d + ncol + 1);
                    float2 f0 = __half22float2(*(__half2*)&acc[ni][0]);
                    float2 f1 = __half22float2(*(__half2*)&acc[ni][1]);
                    float z0 = f0.x + bv0, z1 = f0.y + bv1;
                    float z2 = f1.x + bv0, z3 = f1.y + bv1;
                    float e0 = __expf(z0), e1 = __expf(z1);
                    float e2 = __expf(z2), e3 = __expf(z3);
                    sd0 += e0 + e1;
                    sd1 += e2 + e3;
                    sz0 += z0 + z1;
                    sz1 += z2 + z3;
                    rs[r0 * RSTRIDE + ncol]     = __float2half_rn(rsqrtf(e0));
                    rs[r0 * RSTRIDE + ncol + 1] = __float2half_rn(rsqrtf(e1));
                    rs[r1 * RSTRIDE + ncol]     = __float2half_rn(rsqrtf(e2));
                    rs[r1 * RSTRIDE + ncol + 1] = __float2half_rn(rsqrtf(e3));
                }
                sd0 += __shfl_xor_sync(~0u, sd0, 1); sd0 += __shfl_xor_sync(~0u, sd0, 2);
                sd1 += __shfl_xor_sync(~0u, sd1, 1); sd1 += __shfl_xor_sync(~0u, sd1, 2);
                sz0 += __shfl_xor_sync(~0u, sz0, 1); sz0 += __shfl_xor_sync(~0u, sz0, 2);
                sz1 += __shfl_xor_sync(~0u, sz1, 1); sz1 += __shfl_xor_sync(~0u, sz1, 2);
                if (q == 0) {
                    atomicAdd(&stats[r0 * NSTATS + 1], sd0);
                    atomicAdd(&stats[r1 * NSTATS + 1], sd1);
                    atomicAdd(&stats[r0 * NSTATS + 2], sz0);
                    atomicAdd(&stats[r1 * NSTATS + 2], sz1);
                }
            } else {
                const int ubase = nb_tab[ch] - 128;
                float su0 = 0.f, su1 = 0.f;
                float mac0[10], mac1[10];
                #pragma unroll
                for (int i = 0; i < 10; i++) { mac0[i] = 0.f; mac1[i] = 0.f; }
                #pragma unroll
                for (int ni = 0; ni < 8; ni++) {
                    int ncol = nh * 64 + ni * 8 + q * 2;
                    int gcol = ubase + ncol;                  // global u column = l*4 + r
                    float bv0 = __ldg(b_u + gcol), bv1 = __ldg(b_u + gcol + 1);
                    float2 f0 = __half22float2(*(__half2*)&acc[ni][0]);
                    float2 f1 = __half22float2(*(__half2*)&acc[ni][1]);
                    float u0 = f0.x + bv0, u1 = f0.y + bv1;
                    float u2 = f1.x + bv0, u3 = f1.y + bv1;
                    su0 += u0 * u0 + u1 * u1;
                    su1 += u2 * u2 + u3 * u3;
                    int l = gcol >> 2;
                    float rv0 = __half2float(rs[r0 * RSTRIDE + l]);
                    float rv1 = __half2float(rs[r1 * RSTRIDE + l]);
                    float m0 = u0 * rv0, m1 = u1 * rv0;       // even q: ranks (0,1); odd q: (2,3)
                    float m2 = u2 * rv1, m3 = u3 * rv1;
                    float p0 = __shfl_xor_sync(~0u, m0, 1);
                    float p1 = __shfl_xor_sync(~0u, m1, 1);
                    float p2 = __shfl_xor_sync(~0u, m2, 1);
                    float p3 = __shfl_xor_sync(~0u, m3, 1);
                    float v0[4] = { m0, m1, p0, p1 };
                    float v1[4] = { m2, m3, p2, p3 };
                    #pragma unroll
                    for (int i2 = 0; i2 < 4; i2++)
                        #pragma unroll
                        for (int j2 = 0; j2 <= i2; j2++) {
                            mac0[i2 * (i2 + 1) / 2 + j2] += v0[i2] * v0[j2];
                            mac1[i2 * (i2 + 1) / 2 + j2] += v1[i2] * v1[j2];
                        }
                }
                su0 += __shfl_xor_sync(~0u, su0, 1); su0 += __shfl_xor_sync(~0u, su0, 2);
                su1 += __shfl_xor_sync(~0u, su1, 1); su1 += __shfl_xor_sync(~0u, su1, 2);
                #pragma unroll
                for (int i = 0; i < 10; i++) {    // combine even-latent (q0) + odd-latent (q2)
                    mac0[i] += __shfl_xor_sync(~0u, mac0[i], 2);
                    mac1[i] += __shfl_xor_sync(~0u, mac1[i], 2);
                }
                if (q == 0) {
                    atomicAdd(&stats[r0 * NSTATS + 3], su0);
                    atomicAdd(&stats[r1 * NSTATS + 3], su1);
                    #pragma unroll
                    for (int i = 0; i < 10; i++) {
                        atomicAdd(&stats[r0 * NSTATS + 4 + i], mac0[i]);
                        atomicAdd(&stats[r1 * NSTATS + 4 + i], mac1[i]);
                    }
                }
            }
        }

        // single barrier: makes W stage s+1 AND x tile s+1 visible; frees slot of stage s
        if (s + 2 < NSTAGES) { CP_WAIT(1); } else { CP_WAIT(0); }
        __syncthreads();
    }

    // ---- per-row finish: logdet(I + MtM) via 4x4 Cholesky, then KL ----
    double klsum = 0.0;
    if (tid < MROWS) {
        const float* st = stats + tid * NSTATS;
        float mu_sq = st[0], sum_d = st[1], logz = st[2], su = st[3];
        float a00 = 1.f + st[4];
        float a10 = st[5],  a11 = 1.f + st[6];
        float a20 = st[7],  a21 = st[8],  a22 = 1.f + st[9];
        float a30 = st[10], a31 = st[11], a32 = st[12], a33 = 1.f + st[13];
        float L00 = sqrtf(a00); float i0 = 1.f / L00;
        float L10 = a10 * i0, L20 = a20 * i0, L30 = a30 * i0;
        float L11 = sqrtf(a11 - L10 * L10); float i1 = 1.f / L11;
        float L21 = (a21 - L20 * L10) * i1;
        float L31 = (a31 - L30 * L10) * i1;
        float L22 = sqrtf(a22 - L20 * L20 - L21 * L21); float i2 = 1.f / L22;
        float L32 = (a32 - L30 * L20 - L31 * L21) * i2;
        float L33 = sqrtf(a33 - L30 * L30 - L31 * L31 - L32 * L32);
        float logdetlr = 2.f * (logf(L00) + logf(L11) + logf(L22) + logf(L33));
        float kl = 0.5f * (sum_d + su + mu_sq - (float)LATENT - logz - logdetlr);
        klsum = (double)kl;
    }
    #pragma unroll
    for (int off = 16; off; off >>= 1) klsum += __shfl_down_sync(~0u, klsum, off);
    __shared__ double wsum[16];
    if (lane == 0) wsum[wid] = klsum;
    __syncthreads();
    if (tid == 0) {
        double ssum = 0.0;
        #pragma unroll
        for (int i = 0; i < 16; i++) ssum += wsum[i];
        atomicAdd(&g_sum, ssum);
        __threadfence();
        unsigned done = atomicAdd(&g_done, 1u);
        if (done == gridDim.x - 1) {               // last CTA writes the mean
            __threadfence();
            out[0] = (float)(g_sum / (double)Ntot);
        }
    }
}

extern "C" void kernel_launch(void* const* d_in, const int* in_sizes, int n_in,
                              void* d_out, int out_size) {
    const float* x    = (const float*)d_in[0];
    const float* W_mu = (const float*)d_in[1];
    const float* b_mu = (const float*)d_in[2];
    const float* W_u  = (const float*)d_in[3];
    const float* b_u  = (const float*)d_in[4];
    const float* W_d  = (const float*)d_in[5];
    const float* b_d  = (const float*)d_in[6];
    const int N = in_sizes[0] / HIDDEN;

    const size_t smem_bytes =
        (size_t)(MROWS * XSTRIDE + NRING * WS_ELEMS + 128 * RSTRIDE) * sizeof(__half) +
        (size_t)(128 * NSTATS) * sizeof(float);

    cudaFuncSetAttribute(lrg_main, cudaFuncAttributeMaxDynamicSharedMemorySize,
                         (int)smem_bytes);

    convertW_kernel<<<192, 256>>>(W_mu, W_u, W_d);
    lrg_main<<<N / MROWS, THREADS, smem_bytes>>>(x, b_mu, b_u, b_d, (float*)d_out, N);
}

// round 15
// speedup vs baseline: 1.0321x; 1.0321x over previous
#include <cuda_runtime.h>
#include <cuda_fp16.h>
#include <cstdint>

#define HIDDEN   512
#define LATENT   128
#define NTOT     768          // 128 (mu) + 512 (u) + 128 (d)
#define MROWS    128          // rows per CTA
#define THREADS  256          // 8 warps: 4 m-groups (32 rows) x 2 n-halves (64 cols)
#define KTILE    64
#define XSTRIDE  520          // 512 + 8 fp16 -> conflict-free ldmatrix
#define WSTRIDE  72           // 64 + 8 fp16  -> conflict-free ldmatrix
#define WS_ELEMS (128 * WSTRIDE)       // per stage
#define RSTRIDE  132
#define NSTATS   16
#define NSTAGES  48           // 6 chunks x 8 k-tiles
#define NRING    3

// W fused+transposed fp16, layout [n=768][k=512]: n = [mu 0-127 | u 128-639 | d 640-767]
__device__ __half g_Wt[(size_t)NTOT * HIDDEN];
__device__ double g_sum;
__device__ unsigned g_done;

// Coalesced transpose: 32k x 64n fp32 tile -> [n][k] fp16, via padded smem.
// grid.x = 192 tiles: tile t -> n0 = (t % 12) * 64, k0 = (t / 12) * 32
__global__ void convertW_kernel(const float* __restrict__ W_mu,
                                const float* __restrict__ W_u,
                                const float* __restrict__ W_d) {
    __shared__ float tile_s[32][65];
    const int t  = blockIdx.x;
    const int n0 = (t % 12) * 64;
    const int k0 = (t / 12) * 32;
    if (threadIdx.x == 0 && t == 0) { g_sum = 0.0; g_done = 0u; }

    const float* src; int ld, nloc;
    if (n0 < 128)      { src = W_mu; ld = 128; nloc = n0; }
    else if (n0 < 640) { src = W_u;  ld = 512; nloc = n0 - 128; }
    else               { src = W_d;  ld = 128; nloc = n0 - 640; }

    const int tx = threadIdx.x & 63;
    const int ty = threadIdx.x >> 6;          // 0..3
    #pragma unroll
    for (int i = 0; i < 8; i++) {
        int k = ty + i * 4;
        tile_s[k][tx] = src[(size_t)(k0 + k) * ld + nloc + tx];     // coalesced 64-wide
    }
    __syncthreads();
    const int tx2 = threadIdx.x & 31;
    const int ty2 = threadIdx.x >> 5;          // 0..7
    #pragma unroll
    for (int i = 0; i < 8; i++) {
        int n = ty2 + i * 8;
        g_Wt[(size_t)(n0 + n) * HIDDEN + k0 + tx2] =
            __float2half_rn(tile_s[tx2][n]);                         // coalesced fp16 writes
    }
}

__device__ __forceinline__ unsigned smem_u32(const void* p) {
    return (unsigned)__cvta_generic_to_shared(p);
}
__device__ __forceinline__ void ldsm4(unsigned& r0, unsigned& r1, unsigned& r2, unsigned& r3, unsigned a) {
    asm volatile("ldmatrix.sync.aligned.m8n8.x4.shared.b16 {%0,%1,%2,%3}, [%4];"
                 : "=r"(r0), "=r"(r1), "=r"(r2), "=r"(r3) : "r"(a));
}
// fp16-accumulate HMMA: c0 = row g cols(2q,2q+1), c1 = row g+8
__device__ __forceinline__ void mma16816h(unsigned& c0, unsigned& c1,
                                          unsigned a0, unsigned a1, unsigned a2, unsigned a3,
                                          unsigned b0, unsigned b1) {
    asm volatile("mma.sync.aligned.m16n8k16.row.col.f16.f16.f16.f16 "
                 "{%0,%1},{%2,%3,%4,%5},{%6,%7},{%0,%1};"
                 : "+r"(c0), "+r"(c1)
                 : "r"(a0), "r"(a1), "r"(a2), "r"(a3), "r"(b0), "r"(b1));
}
__device__ __forceinline__ void cpasync16(unsigned dst, const void* src) {
    asm volatile("cp.async.cg.shared.global [%0], [%1], 16;" :: "r"(dst), "l"(src) : "memory");
}
#define CP_COMMIT() asm volatile("cp.async.commit_group;" ::: "memory")
#define CP_WAIT(n)  asm volatile("cp.async.wait_group %0;" :: "n"(n) : "memory")

extern __shared__ char smem_raw[];

__global__ void __launch_bounds__(THREADS, 1)
lrg_main(const float* __restrict__ x,
         const float* __restrict__ b_mu,
         const float* __restrict__ b_u,
         const float* __restrict__ b_d,
         float* __restrict__ out, int Ntot)
{
    // ---- shared memory layout (230,400 B dynamic) ----
    __half* xs = (__half*)smem_raw;                            // [128][XSTRIDE]      133,120 B
    __half* ws = xs + MROWS * XSTRIDE;                         // 3 x [128][WSTRIDE]   55,296 B
    __half* rs = ws + NRING * WS_ELEMS;                        // [128][RSTRIDE]       33,792 B
    float* stats = (float*)(rs + 128 * RSTRIDE);               // [128][NSTATS]         8,192 B

    const int tid  = threadIdx.x;
    const int wid  = tid >> 5;
    const int lane = tid & 31;
    const int mw   = wid & 3;          // M group: 32 rows
    const int nh   = wid >> 2;         // N half: 64 cols
    const int q    = lane & 3;
    const int g    = lane >> 2;
    const int rowbase = blockIdx.x * MROWS;

    // rows of fragment rf = mg*2 + rh: mw*32 + mg*16 + rh*8 + g
    int rowf[4];
    #pragma unroll
    for (int rf = 0; rf < 4; rf++)
        rowf[rf] = mw * 32 + (rf >> 1) * 16 + ((rf & 1) << 3) + g;

    for (int i = tid; i < 128 * NSTATS; i += THREADS) stats[i] = 0.f;

    const unsigned xs_base = smem_u32(xs);
    const unsigned ws_base = smem_u32(ws);
    const float4* xg = (const float4*)(x + (size_t)rowbase * HIDDEN);

    // chunk order: mu, d, u0..u3 (d before u so rsqrt(d) ready)
    const int nb_tab[6] = {0, 640, 128, 256, 384, 512};

    // cp.async producer for one stage: W tile [128n][64k] -> ring slot
    auto issue_stage = [&](int s) {
        const int slot = s % NRING;
        const int nb = nb_tab[s >> 3];
        const int kt = s & 7;
        const __half* srcb = g_Wt + (size_t)nb * HIDDEN + kt * KTILE;
        const unsigned dbase = ws_base + (unsigned)(slot * WS_ELEMS * 2);
        #pragma unroll
        for (int c = tid; c < 1024; c += THREADS) {      // 4 iters x 16B
            int n  = c >> 3;
            int k8 = c & 7;
            cpasync16(dbase + (unsigned)(n * (WSTRIDE * 2) + k8 * 16),
                      srcb + (size_t)n * HIDDEN + k8 * 8);
        }
        CP_COMMIT();
    };

    // x k-tile loader: tile xt covers cols [xt*64, xt*64+64); 8 float4 per thread
    auto load_x_tile = [&](int xt) {
        #pragma unroll
        for (int j = 0; j < 8; j++) {
            int idx = tid + j * THREADS;        // 2048 float4 per tile
            int row = idx >> 4;                 // 16 float4 per row-tile
            int c4  = idx & 15;
            float4 v = xg[row * 128 + xt * 16 + c4];
            __half2* dst = (__half2*)(xs + row * XSTRIDE + xt * 64 + c4 * 4);
            dst[0] = __floats2half2_rn(v.x, v.y);
            dst[1] = __floats2half2_rn(v.z, v.w);
        }
    };

    // W stages 0,1 in flight, then ONLY x tile 0 (rest staged inside chunk 0)
    issue_stage(0);
    issue_stage(1);
    load_x_tile(0);
    CP_WAIT(1);
    __syncthreads();

    // ---- ldmatrix per-lane addressing ----
    const int t8 = lane >> 3;
    const int ri = lane & 7;
    // A (m16 group mg): rows mw*32 + mg*16 + (t8&1)*8 + ri, k + ((t8>>1)&1)*8
    const unsigned a_addr_m0 = xs_base +
        (unsigned)(((mw * 32 + ((t8 & 1) << 3) + ri) * XSTRIDE + (((t8 >> 1) & 1) << 3)) * 2);
    const unsigned a_addr_m1 = a_addr_m0 + (unsigned)(16 * XSTRIDE * 2);
    // B: n = nh*64 + p*16 + ((t8>>1)&1)*8 + ri, k + (t8&1)*8
    const unsigned b_addr0 = ws_base +
        (unsigned)(((nh * 64 + (((t8 >> 1) & 1) << 3) + ri) * WSTRIDE + ((t8 & 1) << 3)) * 2);

    // acc[mg*8 + ni][rh] = row rowf[mg*2+rh], col nh*64 + ni*8 + q*2
    unsigned acc[16][2];

    #pragma unroll 1
    for (int s = 0; s < NSTAGES; s++) {
        const int slot = s % NRING;
        const int ch = s >> 3;
        const int kt = s & 7;

        if (kt == 0) {
            #pragma unroll
            for (int i = 0; i < 16; i++) { acc[i][0] = 0u; acc[i][1] = 0u; }
        }

        // -------- MMA block: 24 ldsm.x4 + 64 HMMA per warp --------
        const unsigned b_st = b_addr0 + (unsigned)(slot * WS_ELEMS * 2);
        const int k0 = kt * KTILE;
        #pragma unroll
        for (int ks = 0; ks < 4; ks++) {
            unsigned a00, a01, a02, a03, a10, a11, a12, a13;
            ldsm4(a00, a01, a02, a03, a_addr_m0 + (unsigned)((k0 + ks * 16) * 2));
            ldsm4(a10, a11, a12, a13, a_addr_m1 + (unsigned)((k0 + ks * 16) * 2));
            #pragma unroll
            for (int p = 0; p < 4; p++) {
                unsigned b0, b1, b2, b3;
                ldsm4(b0, b1, b2, b3,
                      b_st + (unsigned)(p * 16 * WSTRIDE * 2 + ks * 16 * 2));
                mma16816h(acc[p * 2 + 0][0],     acc[p * 2 + 0][1],     a00, a01, a02, a03, b0, b1);
                mma16816h(acc[p * 2 + 1][0],     acc[p * 2 + 1][1],     a00, a01, a02, a03, b2, b3);
                mma16816h(acc[8 + p * 2 + 0][0], acc[8 + p * 2 + 0][1], a10, a11, a12, a13, b0, b1);
                mma16816h(acc[8 + p * 2 + 1][0], acc[8 + p * 2 + 1][1], a10, a11, a12, a13, b2, b3);
            }
        }

        // issue next+1 W stage into the slot stage s-1 used
        if (s + 2 < NSTAGES) issue_stage(s + 2);
        // progressive x staging: during chunk-0 stage kt, fetch x tile kt+1
        if (s < 7) load_x_tile(s + 1);

        if (kt == 7) {
            // ================= fused epilogue for chunk ch =================
            // acc[mg*8+ni][rh]: row rowf[mg*2+rh], col nh*64 + ni*8 + q*2 + {0,1}
            if (ch == 0) {
                float sA[4] = {0.f, 0.f, 0.f, 0.f};
                #pragma unroll
                for (int mg = 0; mg < 2; mg++)
                    #pragma unroll
                    for (int ni = 0; ni < 8; ni++) {
                        int ncol = nh * 64 + ni * 8 + q * 2;
                        float bv0 = __ldg(b_mu + ncol), bv1 = __ldg(b_mu + ncol + 1);
                        #pragma unroll
                        for (int rh = 0; rh < 2; rh++) {
                            float2 f = __half22float2(*(__half2*)&acc[mg * 8 + ni][rh]);
                            float v0 = f.x + bv0, v1 = f.y + bv1;
                            sA[mg * 2 + rh] += v0 * v0 + v1 * v1;
                        }
                    }
                #pragma unroll
                for (int rf = 0; rf < 4; rf++) {
                    float v = sA[rf];
                    v += __shfl_xor_sync(~0u, v, 1); v += __shfl_xor_sync(~0u, v, 2);
                    if (q == 0) atomicAdd(&stats[rowf[rf] * NSTATS + 0], v);
                }
            } else if (ch == 1) {
                float sD[4] = {0.f, 0.f, 0.f, 0.f};
                float sZ[4] = {0.f, 0.f, 0.f, 0.f};
                #pragma unroll
                for (int mg = 0; mg < 2; mg++)
                    #pragma unroll
                    for (int ni = 0; ni < 8; ni++) {
                        int ncol = nh * 64 + ni * 8 + q * 2;
                        float bv0 = __ldg(b_d + ncol), bv1 = __ldg(b_d + ncol + 1);
                        #pragma unroll
                        for (int rh = 0; rh < 2; rh++) {
                            int rf = mg * 2 + rh;
                            float2 f = __half22float2(*(__half2*)&acc[mg * 8 + ni][rh]);
                            float z0 = f.x + bv0, z1 = f.y + bv1;
                            float e0 = __expf(z0), e1 = __expf(z1);
                            sD[rf] += e0 + e1;
                            sZ[rf] += z0 + z1;
                            rs[rowf[rf] * RSTRIDE + ncol]     = __float2half_rn(rsqrtf(e0));
                            rs[rowf[rf] * RSTRIDE + ncol + 1] = __float2half_rn(rsqrtf(e1));
                        }
                    }
                #pragma unroll
                for (int rf = 0; rf < 4; rf++) {
                    float vd = sD[rf], vz = sZ[rf];
                    vd += __shfl_xor_sync(~0u, vd, 1); vd += __shfl_xor_sync(~0u, vd, 2);
                    vz += __shfl_xor_sync(~0u, vz, 1); vz += __shfl_xor_sync(~0u, vz, 2);
                    if (q == 0) {
                        atomicAdd(&stats[rowf[rf] * NSTATS + 1], vd);
                        atomicAdd(&stats[rowf[rf] * NSTATS + 2], vz);
                    }
                }
            } else {
                const int ubase = nb_tab[ch] - 128;
                float sU[4] = {0.f, 0.f, 0.f, 0.f};
                float mac[4][10];
                #pragma unroll
                for (int rf = 0; rf < 4; rf++)
                    #pragma unroll
                    for (int i = 0; i < 10; i++) mac[rf][i] = 0.f;
                #pragma unroll
                for (int mg = 0; mg < 2; mg++)
                    #pragma unroll
                    for (int ni = 0; ni < 8; ni++) {
                        int ncol = nh * 64 + ni * 8 + q * 2;
                        int gcol = ubase + ncol;              // global u column = l*4 + r
                        int l = gcol >> 2;
                        float bv0 = __ldg(b_u + gcol), bv1 = __ldg(b_u + gcol + 1);
                        #pragma unroll
                        for (int rh = 0; rh < 2; rh++) {
                            int rf = mg * 2 + rh;
                            float2 f = __half22float2(*(__half2*)&acc[mg * 8 + ni][rh]);
                            float u0 = f.x + bv0, u1 = f.y + bv1;
                            sU[rf] += u0 * u0 + u1 * u1;
                            float rv = __half2float(rs[rowf[rf] * RSTRIDE + l]);
                            float m0 = u0 * rv, m1 = u1 * rv; // even q: ranks(0,1); odd: (2,3)
                            float p0 = __shfl_xor_sync(~0u, m0, 1);
                            float p1 = __shfl_xor_sync(~0u, m1, 1);
                            float v[4] = { m0, m1, p0, p1 };  // valid ordering on even q
                            #pragma unroll
                            for (int i2 = 0; i2 < 4; i2++)
                                #pragma unroll
                                for (int j2 = 0; j2 <= i2; j2++)
                                    mac[rf][i2 * (i2 + 1) / 2 + j2] += v[i2] * v[j2];
                        }
                    }
                #pragma unroll
                for (int rf = 0; rf < 4; rf++) {
                    float v = sU[rf];
                    v += __shfl_xor_sync(~0u, v, 1); v += __shfl_xor_sync(~0u, v, 2);
                    if (q == 0) atomicAdd(&stats[rowf[rf] * NSTATS + 3], v);
                    #pragma unroll
                    for (int i = 0; i < 10; i++) {
                        float m = mac[rf][i] + __shfl_xor_sync(~0u, mac[rf][i], 2);
                        if (q == 0) atomicAdd(&stats[rowf[rf] * NSTATS + 4 + i], m);
                    }
                }
            }
        }

        // single barrier: makes W stage s+1 AND x tile s+1 visible; frees slot of stage s
        if (s + 2 < NSTAGES) { CP_WAIT(1); } else { CP_WAIT(0); }
        __syncthreads();
    }

    // ---- per-row finish: logdet(I + MtM) via 4x4 Cholesky, then KL ----
    double klsum = 0.0;
    if (tid < MROWS) {
        const float* st = stats + tid * NSTATS;
        float mu_sq = st[0], sum_d = st[1], logz = st[2], su = st[3];
        float a00 = 1.f + st[4];
        float a10 = st[5],  a11 = 1.f + st[6];
        float a20 = st[7],  a21 = st[8],  a22 = 1.f + st[9];
        float a30 = st[10], a31 = st[11], a32 = st[12], a33 = 1.f + st[13];
        float L00 = sqrtf(a00); float i0 = 1.f / L00;
        float L10 = a10 * i0, L20 = a20 * i0, L30 = a30 * i0;
        float L11 = sqrtf(a11 - L10 * L10); float i1 = 1.f / L11;
        float L21 = (a21 - L20 * L10) * i1;
        float L31 = (a31 - L30 * L10) * i1;
        float L22 = sqrtf(a22 - L20 * L20 - L21 * L21); float i2 = 1.f / L22;
        float L32 = (a32 - L30 * L20 - L31 * L21) * i2;
        float L33 = sqrtf(a33 - L30 * L30 - L31 * L31 - L32 * L32);
        float logdetlr = 2.f * (logf(L00) + logf(L11) + logf(L22) + logf(L33));
        float kl = 0.5f * (sum_d + su + mu_sq - (float)LATENT - logz - logdetlr);
        klsum = (double)kl;
    }
    #pragma unroll
    for (int off = 16; off; off >>= 1) klsum += __shfl_down_sync(~0u, klsum, off);
    __shared__ double wsum[8];
    if (lane == 0) wsum[wid] = klsum;
    __syncthreads();
    if (tid == 0) {
        double ssum = 0.0;
        #pragma unroll
        for (int i = 0; i < 8; i++) ssum += wsum[i];
        atomicAdd(&g_sum, ssum);
        __threadfence();
        unsigned done = atomicAdd(&g_done, 1u);
        if (done == gridDim.x - 1) {               // last CTA writes the mean
            __threadfence();
            out[0] = (float)(g_sum / (double)Ntot);
        }
    }
}

extern "C" void kernel_launch(void* const* d_in, const int* in_sizes, int n_in,
                              void* d_out, int out_size) {
    const float* x    = (const float*)d_in[0];
    const float* W_mu = (const float*)d_in[1];
    const float* b_mu = (const float*)d_in[2];
    const float* W_u  = (const float*)d_in[3];
    const float* b_u  = (const float*)d_in[4];
    const float* W_d  = (const float*)d_in[5];
    const float* b_d  = (const float*)d_in[6];
    const int N = in_sizes[0] / HIDDEN;

    const size_t smem_bytes =
        (size_t)(MROWS * XSTRIDE + NRING * WS_ELEMS + 128 * RSTRIDE) * sizeof(__half) +
        (size_t)(128 * NSTATS) * sizeof(float);

    cudaFuncSetAttribute(lrg_main, cudaFuncAttributeMaxDynamicSharedMemorySize,
                         (int)smem_bytes);

    convertW_kernel<<<192, 256>>>(W_mu, W_u, W_d);
    lrg_main<<<N / MROWS, THREADS, smem_bytes>>>(x, b_mu, b_u, b_d, (float*)d_out, N);
}

// round 16
// speedup vs baseline: 1.1723x; 1.1359x over previous
#include <cuda_runtime.h>
#include <cuda_fp16.h>
#include <cstdint>

#define HIDDEN   512
#define LATENT   128
#define NTOT     768          // 128 (mu) + 512 (u) + 128 (d)
#define MROWS    128          // rows per CTA
#define THREADS  256
#define KTILE    64
#define XSTRIDE  520          // 512 + 8 fp16 -> conflict-free ldmatrix
#define WSTRIDE  72           // 64 + 8 fp16  -> conflict-free ldmatrix
#define WS_ELEMS (128 * WSTRIDE)       // per stage
#define RSTRIDE  132
#define NSTATS   16
#define NSTAGES  48           // 6 chunks x 8 k-tiles
#define NRING    3

// W fused+transposed fp16, layout [n=768][k=512]: n = [mu 0-127 | u 128-639 | d 640-767]
__device__ __half g_Wt[(size_t)NTOT * HIDDEN];
__device__ double g_sum;
__device__ unsigned g_done;

// Coalesced transpose: 32k x 64n fp32 tile -> [n][k] fp16, via padded smem.
// grid.x = 192 tiles: tile t -> n0 = (t % 12) * 64, k0 = (t / 12) * 32
__global__ void convertW_kernel(const float* __restrict__ W_mu,
                                const float* __restrict__ W_u,
                                const float* __restrict__ W_d) {
    __shared__ float tile_s[32][65];
    const int t  = blockIdx.x;
    const int n0 = (t % 12) * 64;
    const int k0 = (t / 12) * 32;
    if (threadIdx.x == 0 && t == 0) { g_sum = 0.0; g_done = 0u; }

    const float* src; int ld, nloc;
    if (n0 < 128)      { src = W_mu; ld = 128; nloc = n0; }
    else if (n0 < 640) { src = W_u;  ld = 512; nloc = n0 - 128; }
    else               { src = W_d;  ld = 128; nloc = n0 - 640; }

    const int tx = threadIdx.x & 63;
    const int ty = threadIdx.x >> 6;          // 0..3
    #pragma unroll
    for (int i = 0; i < 8; i++) {
        int k = ty + i * 4;
        tile_s[k][tx] = src[(size_t)(k0 + k) * ld + nloc + tx];     // coalesced 64-wide
    }
    __syncthreads();
    const int tx2 = threadIdx.x & 31;
    const int ty2 = threadIdx.x >> 5;          // 0..7
    #pragma unroll
    for (int i = 0; i < 8; i++) {
        int n = ty2 + i * 8;
        g_Wt[(size_t)(n0 + n) * HIDDEN + k0 + tx2] =
            __float2half_rn(tile_s[tx2][n]);                         // coalesced fp16 writes
    }
}

__device__ __forceinline__ unsigned smem_u32(const void* p) {
    return (unsigned)__cvta_generic_to_shared(p);
}
__device__ __forceinline__ void ldsm4(unsigned& r0, unsigned& r1, unsigned& r2, unsigned& r3, unsigned a) {
    asm volatile("ldmatrix.sync.aligned.m8n8.x4.shared.b16 {%0,%1,%2,%3}, [%4];"
                 : "=r"(r0), "=r"(r1), "=r"(r2), "=r"(r3) : "r"(a));
}
// fp16-accumulate HMMA: c0 = row g cols(2q,2q+1), c1 = row g+8
__device__ __forceinline__ void mma16816h(unsigned& c0, unsigned& c1,
                                          unsigned a0, unsigned a1, unsigned a2, unsigned a3,
                                          unsigned b0, unsigned b1) {
    asm volatile("mma.sync.aligned.m16n8k16.row.col.f16.f16.f16.f16 "
                 "{%0,%1},{%2,%3,%4,%5},{%6,%7},{%0,%1};"
                 : "+r"(c0), "+r"(c1)
                 : "r"(a0), "r"(a1), "r"(a2), "r"(a3), "r"(b0), "r"(b1));
}
__device__ __forceinline__ void cpasync16(unsigned dst, const void* src) {
    asm volatile("cp.async.cg.shared.global [%0], [%1], 16;" :: "r"(dst), "l"(src) : "memory");
}
#define CP_COMMIT() asm volatile("cp.async.commit_group;" ::: "memory")
#define CP_WAIT(n)  asm volatile("cp.async.wait_group %0;" :: "n"(n) : "memory")

extern __shared__ char smem_raw[];

__global__ void __launch_bounds__(THREADS, 1)
lrg_main(const float* __restrict__ x,
         const float* __restrict__ b_mu,
         const float* __restrict__ b_u,
         const float* __restrict__ b_d,
         float* __restrict__ out, int Ntot)
{
    // ---- shared memory layout (230,400 B dynamic) ----
    __half* xs = (__half*)smem_raw;                            // [128][XSTRIDE]      133,120 B
    __half* ws = xs + MROWS * XSTRIDE;                         // 3 x [128][WSTRIDE]   55,296 B
    __half* rs = ws + NRING * WS_ELEMS;                        // [128][RSTRIDE]       33,792 B
    float* stats = (float*)(rs + 128 * RSTRIDE);               // [128][NSTATS]         8,192 B

    const int tid  = threadIdx.x;
    const int wid  = tid >> 5;
    const int lane = tid & 31;
    const int q    = lane & 3;
    const int g    = lane >> 2;
    const int r0   = wid * 16 + g;
    const int r1   = r0 + 8;
    const int rowbase = blockIdx.x * MROWS;

    for (int i = tid; i < 128 * NSTATS; i += THREADS) stats[i] = 0.f;

    const unsigned xs_base = smem_u32(xs);
    const unsigned ws_base = smem_u32(ws);
    const float4* xg = (const float4*)(x + (size_t)rowbase * HIDDEN);

    // chunk order: mu, d, u0..u3 (d before u so rsqrt(d) ready)
    const int nb_tab[6] = {0, 640, 128, 256, 384, 512};

    // cp.async producer for one stage: W tile [128n][64k] -> ring slot
    auto issue_stage = [&](int s) {
        const int slot = s % NRING;
        const int nb = nb_tab[s >> 3];
        const int kt = s & 7;
        const __half* srcb = g_Wt + (size_t)nb * HIDDEN + kt * KTILE;
        const unsigned dbase = ws_base + (unsigned)(slot * WS_ELEMS * 2);
        #pragma unroll
        for (int c = tid; c < 1024; c += THREADS) {      // 4 iters x 16B
            int n  = c >> 3;
            int k8 = c & 7;
            cpasync16(dbase + (unsigned)(n * (WSTRIDE * 2) + k8 * 16),
                      srcb + (size_t)n * HIDDEN + k8 * 8);
        }
        CP_COMMIT();
    };

    // x k-tile loader: tile xt covers cols [xt*64, xt*64+64); 8 float4 per thread
    auto load_x_tile = [&](int xt) {
        #pragma unroll
        for (int j = 0; j < 8; j++) {
            int idx = tid + j * THREADS;        // 2048 float4 per tile
            int row = idx >> 4;                 // 16 float4 per row-tile
            int c4  = idx & 15;
            float4 v = xg[row * 128 + xt * 16 + c4];
            __half2* dst = (__half2*)(xs + row * XSTRIDE + xt * 64 + c4 * 4);
            dst[0] = __floats2half2_rn(v.x, v.y);
            dst[1] = __floats2half2_rn(v.z, v.w);
        }
    };

    // W stages 0,1 in flight, then ONLY x tile 0 (rest staged inside chunk 0)
    issue_stage(0);
    issue_stage(1);
    load_x_tile(0);
    CP_WAIT(1);
    __syncthreads();

    // ---- ldmatrix per-lane addressing ----
    const int t8 = lane >> 3;
    const int ri = lane & 7;
    const unsigned a_addr0 = xs_base +
        (unsigned)(((wid * 16 + ((t8 & 1) << 3) + ri) * XSTRIDE + (((t8 >> 1) & 1) << 3)) * 2);
    const unsigned b_addr0 = ws_base +
        (unsigned)((((((t8 >> 1) & 1) << 3) + ri) * WSTRIDE + ((t8 & 1) << 3)) * 2);

    unsigned acc[16][2];

    #pragma unroll 1
    for (int s = 0; s < NSTAGES; s++) {
        const int slot = s % NRING;
        const int ch = s >> 3;
        const int kt = s & 7;

        if (kt == 0) {
            #pragma unroll
            for (int i = 0; i < 16; i++) { acc[i][0] = 0u; acc[i][1] = 0u; }
        }

        const unsigned b_st = b_addr0 + (unsigned)(slot * WS_ELEMS * 2);
        const int k0 = kt * KTILE;
        #pragma unroll
        for (int ks = 0; ks < 4; ks++) {
            unsigned a0, a1, a2, a3;
            ldsm4(a0, a1, a2, a3, a_addr0 + (unsigned)((k0 + ks * 16) * 2));
            #pragma unroll
            for (int p = 0; p < 8; p++) {
                unsigned b0, b1, b2, b3;
                ldsm4(b0, b1, b2, b3,
                      b_st + (unsigned)(p * 16 * WSTRIDE * 2 + ks * 16 * 2));
                mma16816h(acc[2 * p][0],     acc[2 * p][1],     a0, a1, a2, a3, b0, b1);
                mma16816h(acc[2 * p + 1][0], acc[2 * p + 1][1], a0, a1, a2, a3, b2, b3);
            }
        }

        // issue next+1 W stage into the slot stage s-1 used
        if (s + 2 < NSTAGES) issue_stage(s + 2);
        // progressive x staging: during chunk-0 stage kt, fetch x tile kt+1
        if (s < 7) load_x_tile(s + 1);

        if (kt == 7) {
            // ================= fused epilogue for chunk ch =================
            if (ch == 0) {
                float s0 = 0.f, s1 = 0.f;
                #pragma unroll
                for (int ni = 0; ni < 16; ni++) {
                    int ncol = ni * 8 + q * 2;
                    float bv0 = __ldg(b_mu + ncol), bv1 = __ldg(b_mu + ncol + 1);
                    float2 f0 = __half22float2(*(__half2*)&acc[ni][0]);
                    float2 f1 = __half22float2(*(__half2*)&acc[ni][1]);
                    float v0 = f0.x + bv0, v1 = f0.y + bv1;
                    float v2 = f1.x + bv0, v3 = f1.y + bv1;
                    s0 += v0 * v0 + v1 * v1;
                    s1 += v2 * v2 + v3 * v3;
                }
                s0 += __shfl_xor_sync(~0u, s0, 1); s0 += __shfl_xor_sync(~0u, s0, 2);
                s1 += __shfl_xor_sync(~0u, s1, 1); s1 += __shfl_xor_sync(~0u, s1, 2);
                if (q == 0) { stats[r0 * NSTATS + 0] += s0; stats[r1 * NSTATS + 0] += s1; }
            } else if (ch == 1) {
                float sd0 = 0.f, sd1 = 0.f, sz0 = 0.f, sz1 = 0.f;
                #pragma unroll
                for (int ni = 0; ni < 16; ni++) {
                    int ncol = ni * 8 + q * 2;
                    float bv0 = __ldg(b_d + ncol), bv1 = __ldg(b_d + ncol + 1);
                    float2 f0 = __half22float2(*(__half2*)&acc[ni][0]);
                    float2 f1 = __half22float2(*(__half2*)&acc[ni][1]);
                    float z0 = f0.x + bv0, z1 = f0.y + bv1;
                    float z2 = f1.x + bv0, z3 = f1.y + bv1;
                    float e0 = __expf(z0), e1 = __expf(z1);
                    float e2 = __expf(z2), e3 = __expf(z3);
                    sd0 += e0 + e1;
                    sd1 += e2 + e3;
                    sz0 += z0 + z1;
                    sz1 += z2 + z3;
                    rs[r0 * RSTRIDE + ncol]     = __float2half_rn(rsqrtf(e0));
                    rs[r0 * RSTRIDE + ncol + 1] = __float2half_rn(rsqrtf(e1));
                    rs[r1 * RSTRIDE + ncol]     = __float2half_rn(rsqrtf(e2));
                    rs[r1 * RSTRIDE + ncol + 1] = __float2half_rn(rsqrtf(e3));
                }
                sd0 += __shfl_xor_sync(~0u, sd0, 1); sd0 += __shfl_xor_sync(~0u, sd0, 2);
                sd1 += __shfl_xor_sync(~0u, sd1, 1); sd1 += __shfl_xor_sync(~0u, sd1, 2);
                sz0 += __shfl_xor_sync(~0u, sz0, 1); sz0 += __shfl_xor_sync(~0u, sz0, 2);
                sz1 += __shfl_xor_sync(~0u, sz1, 1); sz1 += __shfl_xor_sync(~0u, sz1, 2);
                if (q == 0) {
                    stats[r0 * NSTATS + 1] += sd0; stats[r1 * NSTATS + 1] += sd1;
                    stats[r0 * NSTATS + 2] += sz0; stats[r1 * NSTATS + 2] += sz1;
                }
            } else {
                const int ubase = nb_tab[ch] - 128;
                float su0 = 0.f, su1 = 0.f;
                float mac0[10], mac1[10];
                #pragma unroll
                for (int i = 0; i < 10; i++) { mac0[i] = 0.f; mac1[i] = 0.f; }
                #pragma unroll
                for (int ni = 0; ni < 16; ni++) {
                    int ncol = ni * 8 + q * 2;
                    int gcol = ubase + ncol;                  // global u column = l*4 + r
                    float bv0 = __ldg(b_u + gcol), bv1 = __ldg(b_u + gcol + 1);
                    float2 f0 = __half22float2(*(__half2*)&acc[ni][0]);
                    float2 f1 = __half22float2(*(__half2*)&acc[ni][1]);
                    float u0 = f0.x + bv0, u1 = f0.y + bv1;
                    float u2 = f1.x + bv0, u3 = f1.y + bv1;
                    su0 += u0 * u0 + u1 * u1;
                    su1 += u2 * u2 + u3 * u3;
                    int l = gcol >> 2;
                    float rv0 = __half2float(rs[r0 * RSTRIDE + l]);
                    float rv1 = __half2float(rs[r1 * RSTRIDE + l]);
                    float m0 = u0 * rv0, m1 = u1 * rv0;       // even q: ranks (0,1); odd q: (2,3)
                    float m2 = u2 * rv1, m3 = u3 * rv1;
                    float p0 = __shfl_xor_sync(~0u, m0, 1);
                    float p1 = __shfl_xor_sync(~0u, m1, 1);
                    float p2 = __shfl_xor_sync(~0u, m2, 1);
                    float p3 = __shfl_xor_sync(~0u, m3, 1);
                    float v0[4] = { m0, m1, p0, p1 };
                    float v1[4] = { m2, m3, p2, p3 };
                    #pragma unroll
                    for (int i2 = 0; i2 < 4; i2++)
                        #pragma unroll
                        for (int j2 = 0; j2 <= i2; j2++) {
                            mac0[i2 * (i2 + 1) / 2 + j2] += v0[i2] * v0[j2];
                            mac1[i2 * (i2 + 1) / 2 + j2] += v1[i2] * v1[j2];
                        }
                }
                su0 += __shfl_xor_sync(~0u, su0, 1); su0 += __shfl_xor_sync(~0u, su0, 2);
                su1 += __shfl_xor_sync(~0u, su1, 1); su1 += __shfl_xor_sync(~0u, su1, 2);
                #pragma unroll
                for (int i = 0; i < 10; i++) {    // combine even-latent (q0) + odd-latent (q2)
                    mac0[i] += __shfl_xor_sync(~0u, mac0[i], 2);
                    mac1[i] += __shfl_xor_sync(~0u, mac1[i], 2);
                }
                if (q == 0) {
                    stats[r0 * NSTATS + 3] += su0;
                    stats[r1 * NSTATS + 3] += su1;
                    #pragma unroll
                    for (int i = 0; i < 10; i++) {
                        stats[r0 * NSTATS + 4 + i] += mac0[i];
                        stats[r1 * NSTATS + 4 + i] += mac1[i];
                    }
                }
            }
        }

        // single barrier: makes W stage s+1 AND x tile s+1 visible; frees slot of stage s
        if (s + 2 < NSTAGES) { CP_WAIT(1); } else { CP_WAIT(0); }
        __syncthreads();
    }

    // ---- per-row finish: logdet(I + MtM) via 4x4 Cholesky, then KL ----
    double klsum = 0.0;
    if (tid < MROWS) {
        const float* st = stats + tid * NSTATS;
        float mu_sq = st[0], sum_d = st[1], logz = st[2], su = st[3];
        float a00 = 1.f + st[4];
        float a10 = st[5],  a11 = 1.f + st[6];
        float a20 = st[7],  a21 = st[8],  a22 = 1.f + st[9];
        float a30 = st[10], a31 = st[11], a32 = st[12], a33 = 1.f + st[13];
        float L00 = sqrtf(a00); float i0 = 1.f / L00;
        float L10 = a10 * i0, L20 = a20 * i0, L30 = a30 * i0;
        float L11 = sqrtf(a11 - L10 * L10); float i1 = 1.f / L11;
        float L21 = (a21 - L20 * L10) * i1;
        float L31 = (a31 - L30 * L10) * i1;
        float L22 = sqrtf(a22 - L20 * L20 - L21 * L21); float i2 = 1.f / L22;
        float L32 = (a32 - L30 * L20 - L31 * L21) * i2;
        float L33 = sqrtf(a33 - L30 * L30 - L31 * L31 - L32 * L32);
        float logdetlr = 2.f * (logf(L00) + logf(L11) + logf(L22) + logf(L33));
        float kl = 0.5f * (sum_d + su + mu_sq - (float)LATENT - logz - logdetlr);
        klsum = (double)kl;
    }
    #pragma unroll
    for (int off = 16; off; off >>= 1) klsum += __shfl_down_sync(~0u, klsum, off);
    __shared__ double wsum[8];
    if (lane == 0) wsum[wid] = klsum;
    __syncthreads();
    if (tid == 0) {
        double ssum = 0.0;
        #pragma unroll
        for (int i = 0; i < 8; i++) ssum += wsum[i];
        atomicAdd(&g_sum, ssum);
        __threadfence();
        unsigned done = atomicAdd(&g_done, 1u);
        if (done == gridDim.x - 1) {               // last CTA writes the mean
            __threadfence();
            out[0] = (float)(g_sum / (double)Ntot);
        }
    }
}

extern "C" void kernel_launch(void* const* d_in, const int* in_sizes, int n_in,
                              void* d_out, int out_size) {
    const float* x    = (const float*)d_in[0];
    const float* W_mu = (const float*)d_in[1];
    const float* b_mu = (const float*)d_in[2];
    const float* W_u  = (const float*)d_in[3];
    const float* b_u  = (const float*)d_in[4];
    const float* W_d  = (const float*)d_in[5];
    const float* b_d  = (const float*)d_in[6];
    const int N = in_sizes[0] / HIDDEN;

    const size_t smem_bytes =
        (size_t)(MROWS * XSTRIDE + NRING * WS_ELEMS + 128 * RSTRIDE) * sizeof(__half) +
        (size_t)(128 * NSTATS) * sizeof(float);

    cudaFuncSetAttribute(lrg_main, cudaFuncAttributeMaxDynamicSharedMemorySize,
                         (int)smem_bytes);

    convertW_kernel<<<192, 256>>>(W_mu, W_u, W_d);
    lrg_main<<<N / MROWS, THREADS, smem_bytes>>>(x, b_mu, b_u, b_d, (float*)d_out, N);
}

// round 17
// speedup vs baseline: 1.1847x; 1.0105x over previous
#include <cuda_runtime.h>
#include <cuda_fp16.h>
#include <cstdint>

#define HIDDEN   512
#define LATENT   128
#define NTOT     768          // 128 (mu) + 512 (u) + 128 (d)
#define MROWS    128          // rows per CTA
#define THREADS  256
#define KTILE    64
#define XSTRIDE  520          // 512 + 8 fp16 -> conflict-free ldmatrix
#define WSTRIDE  72           // 64 + 8 fp16  -> conflict-free ldmatrix
#define WS_ELEMS (128 * WSTRIDE)       // per stage
#define RSTRIDE  132
#define NSTATS   16
#define NSTAGES  48           // 6 chunks x 8 k-tiles
#define NRING    3

// W fused+transposed fp16, layout [n=768][k=512]: n = [mu 0-127 | u 128-639 | d 640-767]
__device__ __half g_Wt[(size_t)NTOT * HIDDEN];
__device__ double g_sum;

// Coalesced transpose: 64k x 64n fp32 tile -> [n][k] fp16, via padded smem.
// grid.x = 96 tiles: tile t -> n0 = (t % 12) * 64, k0 = (t / 12) * 64
__global__ void convertW_kernel(const float* __restrict__ W_mu,
                                const float* __restrict__ W_u,
                                const float* __restrict__ W_d) {
    __shared__ float tile_s[64][65];
    const int t  = blockIdx.x;
    const int n0 = (t % 12) * 64;
    const int k0 = (t / 12) * 64;
    const int tx = threadIdx.x & 63;
    const int ty = threadIdx.x >> 6;
    if (threadIdx.x == 0 && t == 0) g_sum = 0.0;

    const float* src; int ld, nloc;
    if (n0 < 128)      { src = W_mu; ld = 128; nloc = n0; }
    else if (n0 < 640) { src = W_u;  ld = 512; nloc = n0 - 128; }
    else               { src = W_d;  ld = 128; nloc = n0 - 640; }

    #pragma unroll
    for (int i = 0; i < 16; i++) {
        int k = ty + i * 4;
        tile_s[k][tx] = src[(size_t)(k0 + k) * ld + nloc + tx];     // coalesced 64-wide
    }
    __syncthreads();
    #pragma unroll
    for (int i = 0; i < 16; i++) {
        int n = ty + i * 4;
        g_Wt[(size_t)(n0 + n) * HIDDEN + k0 + tx] =
            __float2half_rn(tile_s[tx][n]);                          // coalesced fp16 writes
    }
}

__device__ __forceinline__ unsigned smem_u32(const void* p) {
    return (unsigned)__cvta_generic_to_shared(p);
}
__device__ __forceinline__ void ldsm4(unsigned& r0, unsigned& r1, unsigned& r2, unsigned& r3, unsigned a) {
    asm volatile("ldmatrix.sync.aligned.m8n8.x4.shared.b16 {%0,%1,%2,%3}, [%4];"
                 : "=r"(r0), "=r"(r1), "=r"(r2), "=r"(r3) : "r"(a));
}
// fp16-accumulate HMMA: c0 = row g cols(2q,2q+1), c1 = row g+8
__device__ __forceinline__ void mma16816h(unsigned& c0, unsigned& c1,
                                          unsigned a0, unsigned a1, unsigned a2, unsigned a3,
                                          unsigned b0, unsigned b1) {
    asm volatile("mma.sync.aligned.m16n8k16.row.col.f16.f16.f16.f16 "
                 "{%0,%1},{%2,%3,%4,%5},{%6,%7},{%0,%1};"
                 : "+r"(c0), "+r"(c1)
                 : "r"(a0), "r"(a1), "r"(a2), "r"(a3), "r"(b0), "r"(b1));
}
__device__ __forceinline__ void cpasync16(unsigned dst, const void* src) {
    asm volatile("cp.async.cg.shared.global [%0], [%1], 16;" :: "r"(dst), "l"(src) : "memory");
}
#define CP_COMMIT() asm volatile("cp.async.commit_group;" ::: "memory")
#define CP_WAIT(n)  asm volatile("cp.async.wait_group %0;" :: "n"(n) : "memory")

extern __shared__ char smem_raw[];

__global__ void __launch_bounds__(THREADS, 1)
lrg_main(const float* __restrict__ x,
         const float* __restrict__ b_mu,
         const float* __restrict__ b_u,
         const float* __restrict__ b_d)
{
    // ---- shared memory layout (230,400 B dynamic) ----
    __half* xs = (__half*)smem_raw;                            // [128][XSTRIDE]      133,120 B
    __half* ws = xs + MROWS * XSTRIDE;                         // 3 x [128][WSTRIDE]   55,296 B
    __half* rs = ws + NRING * WS_ELEMS;                        // [128][RSTRIDE]       33,792 B
    float* stats = (float*)(rs + 128 * RSTRIDE);               // [128][NSTATS]         8,192 B

    const int tid  = threadIdx.x;
    const int wid  = tid >> 5;
    const int lane = tid & 31;
    const int q    = lane & 3;
    const int g    = lane >> 2;
    const int r0   = wid * 16 + g;
    const int r1   = r0 + 8;
    const int rowbase = blockIdx.x * MROWS;

    for (int i = tid; i < 128 * NSTATS; i += THREADS) stats[i] = 0.f;

    const unsigned xs_base = smem_u32(xs);
    const unsigned ws_base = smem_u32(ws);
    const float4* xg = (const float4*)(x + (size_t)rowbase * HIDDEN);

    // chunk order: mu, d, u0..u3 (d before u so rsqrt(d) ready)
    const int nb_tab[6] = {0, 640, 128, 256, 384, 512};

    // cp.async producer for one stage: W tile [128n][64k] -> ring slot
    auto issue_stage = [&](int s) {
        const int slot = s % NRING;
        const int nb = nb_tab[s >> 3];
        const int kt = s & 7;
        const __half* srcb = g_Wt + (size_t)nb * HIDDEN + kt * KTILE;
        const unsigned dbase = ws_base + (unsigned)(slot * WS_ELEMS * 2);
        #pragma unroll
        for (int c = tid; c < 1024; c += THREADS) {      // 4 iters x 16B
            int n  = c >> 3;
            int k8 = c & 7;
            cpasync16(dbase + (unsigned)(n * (WSTRIDE * 2) + k8 * 16),
                      srcb + (size_t)n * HIDDEN + k8 * 8);
        }
        CP_COMMIT();
    };

    // x k-tile loader: tile xt covers cols [xt*64, xt*64+64); 8 float4 per thread
    auto load_x_tile = [&](int xt) {
        #pragma unroll
        for (int j = 0; j < 8; j++) {
            int idx = tid + j * THREADS;        // 2048 float4 per tile
            int row = idx >> 4;                 // 16 float4 per row-tile
            int c4  = idx & 15;
            float4 v = xg[row * 128 + xt * 16 + c4];
            __half2* dst = (__half2*)(xs + row * XSTRIDE + xt * 64 + c4 * 4);
            dst[0] = __floats2half2_rn(v.x, v.y);
            dst[1] = __floats2half2_rn(v.z, v.w);
        }
    };

    // W stages 0,1 in flight, then ONLY x tile 0 (rest staged inside chunk 0)
    issue_stage(0);
    issue_stage(1);
    load_x_tile(0);
    CP_WAIT(1);
    __syncthreads();

    // ---- ldmatrix per-lane addressing ----
    const int t8 = lane >> 3;
    const int ri = lane & 7;
    const unsigned a_addr0 = xs_base +
        (unsigned)(((wid * 16 + ((t8 & 1) << 3) + ri) * XSTRIDE + (((t8 >> 1) & 1) << 3)) * 2);
    const unsigned b_addr0 = ws_base +
        (unsigned)((((((t8 >> 1) & 1) << 3) + ri) * WSTRIDE + ((t8 & 1) << 3)) * 2);

    unsigned acc[16][2];

    #pragma unroll 1
    for (int s = 0; s < NSTAGES; s++) {
        const int slot = s % NRING;
        const int ch = s >> 3;
        const int kt = s & 7;

        if (kt == 0) {
            #pragma unroll
            for (int i = 0; i < 16; i++) { acc[i][0] = 0u; acc[i][1] = 0u; }
        }

        // -------- software-pipelined MMA block: ldsm for iter i+1 issued before
        // -------- the HMMAs of iter i, hiding LDSM latency in-warp --------
        const unsigned b_st = b_addr0 + (unsigned)(slot * WS_ELEMS * 2);
        const int k0 = kt * KTILE;
        unsigned A[2][4], B[2][4];
        ldsm4(A[0][0], A[0][1], A[0][2], A[0][3], a_addr0 + (unsigned)(k0 * 2));
        ldsm4(B[0][0], B[0][1], B[0][2], B[0][3], b_st);
        #pragma unroll
        for (int ks = 0; ks < 4; ks++) {
            if (ks < 3)
                ldsm4(A[(ks + 1) & 1][0], A[(ks + 1) & 1][1],
                      A[(ks + 1) & 1][2], A[(ks + 1) & 1][3],
                      a_addr0 + (unsigned)((k0 + (ks + 1) * 16) * 2));
            #pragma unroll
            for (int p = 0; p < 8; p++) {
                const int i  = ks * 8 + p;
                const int nb2 = (i + 1) & 1;
                if (p < 7)
                    ldsm4(B[nb2][0], B[nb2][1], B[nb2][2], B[nb2][3],
                          b_st + (unsigned)((p + 1) * 16 * WSTRIDE * 2 + ks * 16 * 2));
                else if (ks < 3)
                    ldsm4(B[nb2][0], B[nb2][1], B[nb2][2], B[nb2][3],
                          b_st + (unsigned)((ks + 1) * 16 * 2));
                const int ab = ks & 1, bb = i & 1;
                mma16816h(acc[2 * p][0],     acc[2 * p][1],
                          A[ab][0], A[ab][1], A[ab][2], A[ab][3], B[bb][0], B[bb][1]);
                mma16816h(acc[2 * p + 1][0], acc[2 * p + 1][1],
                          A[ab][0], A[ab][1], A[ab][2], A[ab][3], B[bb][2], B[bb][3]);
            }
        }

        // issue next+1 W stage into the slot stage s-1 used
        if (s + 2 < NSTAGES) issue_stage(s + 2);
        // progressive x staging: during chunk-0 stage kt, fetch x tile kt+1
        if (s < 7) load_x_tile(s + 1);

        if (kt == 7) {
            // ================= fused epilogue for chunk ch =================
            if (ch == 0) {
                float s0 = 0.f, s1 = 0.f;
                #pragma unroll
                for (int ni = 0; ni < 16; ni++) {
                    int ncol = ni * 8 + q * 2;
                    float bv0 = __ldg(b_mu + ncol), bv1 = __ldg(b_mu + ncol + 1);
                    float2 f0 = __half22float2(*(__half2*)&acc[ni][0]);
                    float2 f1 = __half22float2(*(__half2*)&acc[ni][1]);
                    float v0 = f0.x + bv0, v1 = f0.y + bv1;
                    float v2 = f1.x + bv0, v3 = f1.y + bv1;
                    s0 += v0 * v0 + v1 * v1;
                    s1 += v2 * v2 + v3 * v3;
                }
                s0 += __shfl_xor_sync(~0u, s0, 1); s0 += __shfl_xor_sync(~0u, s0, 2);
                s1 += __shfl_xor_sync(~0u, s1, 1); s1 += __shfl_xor_sync(~0u, s1, 2);
                if (q == 0) { stats[r0 * NSTATS + 0] += s0; stats[r1 * NSTATS + 0] += s1; }
            } else if (ch == 1) {
                float sd0 = 0.f, sd1 = 0.f, sz0 = 0.f, sz1 = 0.f;
                #pragma unroll
                for (int ni = 0; ni < 16; ni++) {
                    int ncol = ni * 8 + q * 2;
                    float bv0 = __ldg(b_d + ncol), bv1 = __ldg(b_d + ncol + 1);
                    float2 f0 = __half22float2(*(__half2*)&acc[ni][0]);
                    float2 f1 = __half22float2(*(__half2*)&acc[ni][1]);
                    float z0 = f0.x + bv0, z1 = f0.y + bv1;
                    float z2 = f1.x + bv0, z3 = f1.y + bv1;
                    float e0 = __expf(z0), e1 = __expf(z1);
                    float e2 = __expf(z2), e3 = __expf(z3);
                    sd0 += e0 + e1;
                    sd1 += e2 + e3;
                    sz0 += z0 + z1;
                    sz1 += z2 + z3;
                    rs[r0 * RSTRIDE + ncol]     = __float2half_rn(rsqrtf(e0));
                    rs[r0 * RSTRIDE + ncol + 1] = __float2half_rn(rsqrtf(e1));
                    rs[r1 * RSTRIDE + ncol]     = __float2half_rn(rsqrtf(e2));
                    rs[r1 * RSTRIDE + ncol + 1] = __float2half_rn(rsqrtf(e3));
                }
                sd0 += __shfl_xor_sync(~0u, sd0, 1); sd0 += __shfl_xor_sync(~0u, sd0, 2);
                sd1 += __shfl_xor_sync(~0u, sd1, 1); sd1 += __shfl_xor_sync(~0u, sd1, 2);
                sz0 += __shfl_xor_sync(~0u, sz0, 1); sz0 += __shfl_xor_sync(~0u, sz0, 2);
                sz1 += __shfl_xor_sync(~0u, sz1, 1); sz1 += __shfl_xor_sync(~0u, sz1, 2);
                if (q == 0) {
                    stats[r0 * NSTATS + 1] += sd0; stats[r1 * NSTATS + 1] += sd1;
                    stats[r0 * NSTATS + 2] += sz0; stats[r1 * NSTATS + 2] += sz1;
                }
            } else {
                const int ubase = nb_tab[ch] - 128;
                float su0 = 0.f, su1 = 0.f;
                float mac0[10], mac1[10];
                #pragma unroll
                for (int i = 0; i < 10; i++) { mac0[i] = 0.f; mac1[i] = 0.f; }
                #pragma unroll
                for (int ni = 0; ni < 16; ni++) {
                    int ncol = ni * 8 + q * 2;
                    int gcol = ubase + ncol;                  // global u column = l*4 + r
                    float bv0 = __ldg(b_u + gcol), bv1 = __ldg(b_u + gcol + 1);
                    float2 f0 = __half22float2(*(__half2*)&acc[ni][0]);
                    float2 f1 = __half22float2(*(__half2*)&acc[ni][1]);
                    float u0 = f0.x + bv0, u1 = f0.y + bv1;
                    float u2 = f1.x + bv0, u3 = f1.y + bv1;
                    su0 += u0 * u0 + u1 * u1;
                    su1 += u2 * u2 + u3 * u3;
                    int l = gcol >> 2;
                    float rv0 = __half2float(rs[r0 * RSTRIDE + l]);
                    float rv1 = __half2float(rs[r1 * RSTRIDE + l]);
                    float m0 = u0 * rv0, m1 = u1 * rv0;       // even q: ranks (0,1); odd q: (2,3)
                    float m2 = u2 * rv1, m3 = u3 * rv1;
                    float p0 = __shfl_xor_sync(~0u, m0, 1);
                    float p1 = __shfl_xor_sync(~0u, m1, 1);
                    float p2 = __shfl_xor_sync(~0u, m2, 1);
                    float p3 = __shfl_xor_sync(~0u, m3, 1);
                    float v0[4] = { m0, m1, p0, p1 };
                    float v1[4] = { m2, m3, p2, p3 };
                    #pragma unroll
                    for (int i2 = 0; i2 < 4; i2++)
                        #pragma unroll
                        for (int j2 = 0; j2 <= i2; j2++) {
                            mac0[i2 * (i2 + 1) / 2 + j2] += v0[i2] * v0[j2];
                            mac1[i2 * (i2 + 1) / 2 + j2] += v1[i2] * v1[j2];
                        }
                }
                su0 += __shfl_xor_sync(~0u, su0, 1); su0 += __shfl_xor_sync(~0u, su0, 2);
                su1 += __shfl_xor_sync(~0u, su1, 1); su1 += __shfl_xor_sync(~0u, su1, 2);
                #pragma unroll
                for (int i = 0; i < 10; i++) {    // combine even-latent (q0) + odd-latent (q2)
                    mac0[i] += __shfl_xor_sync(~0u, mac0[i], 2);
                    mac1[i] += __shfl_xor_sync(~0u, mac1[i], 2);
                }
                if (q == 0) {
                    stats[r0 * NSTATS + 3] += su0;
                    stats[r1 * NSTATS + 3] += su1;
                    #pragma unroll
                    for (int i = 0; i < 10; i++) {
                        stats[r0 * NSTATS + 4 + i] += mac0[i];
                        stats[r1 * NSTATS + 4 + i] += mac1[i];
                    }
                }
            }
        }

        // single barrier: makes W stage s+1 AND x tile s+1 visible; frees slot of stage s
        if (s + 2 < NSTAGES) { CP_WAIT(1); } else { CP_WAIT(0); }
        __syncthreads();
    }

    // ---- per-row finish: logdet(I + MtM) via 4x4 Cholesky, then KL ----
    double klsum = 0.0;
    if (tid < MROWS) {
        const float* st = stats + tid * NSTATS;
        float mu_sq = st[0], sum_d = st[1], logz = st[2], su = st[3];
        float a00 = 1.f + st[4];
        float a10 = st[5],  a11 = 1.f + st[6];
        float a20 = st[7],  a21 = st[8],  a22 = 1.f + st[9];
        float a30 = st[10], a31 = st[11], a32 = st[12], a33 = 1.f + st[13];
        float L00 = sqrtf(a00); float i0 = 1.f / L00;
        float L10 = a10 * i0, L20 = a20 * i0, L30 = a30 * i0;
        float L11 = sqrtf(a11 - L10 * L10); float i1 = 1.f / L11;
        float L21 = (a21 - L20 * L10) * i1;
        float L31 = (a31 - L30 * L10) * i1;
        float L22 = sqrtf(a22 - L20 * L20 - L21 * L21); float i2 = 1.f / L22;
        float L32 = (a32 - L30 * L20 - L31 * L21) * i2;
        float L33 = sqrtf(a33 - L30 * L30 - L31 * L31 - L32 * L32);
        float logdetlr = 2.f * (logf(L00) + logf(L11) + logf(L22) + logf(L33));
        float kl = 0.5f * (sum_d + su + mu_sq - (float)LATENT - logz - logdetlr);
        klsum = (double)kl;
    }
    #pragma unroll
    for (int off = 16; off; off >>= 1) klsum += __shfl_down_sync(~0u, klsum, off);
    __shared__ double wsum[8];
    if (lane == 0) wsum[wid] = klsum;
    __syncthreads();
    if (tid == 0) {
        double ssum = 0.0;
        #pragma unroll
        for (int i = 0; i < 8; i++) ssum += wsum[i];
        atomicAdd(&g_sum, ssum);
    }
}

__global__ void finalize_kernel(float* out, int N) {
    out[0] = (float)(g_sum / (double)N);
}

extern "C" void kernel_launch(void* const* d_in, const int* in_sizes, int n_in,
                              void* d_out, int out_size) {
    const float* x    = (const float*)d_in[0];
    const float* W_mu = (const float*)d_in[1];
    const float* b_mu = (const float*)d_in[2];
    const float* W_u  = (const float*)d_in[3];
    const float* b_u  = (const float*)d_in[4];
    const float* W_d  = (const float*)d_in[5];
    const float* b_d  = (const float*)d_in[6];
    const int N = in_sizes[0] / HIDDEN;

    const size_t smem_bytes =
        (size_t)(MROWS * XSTRIDE + NRING * WS_ELEMS + 128 * RSTRIDE) * sizeof(__half) +
        (size_t)(128 * NSTATS) * sizeof(float);

    cudaFuncSetAttribute(lrg_main, cudaFuncAttributeMaxDynamicSharedMemorySize,
                         (int)smem_bytes);

    convertW_kernel<<<96, 256>>>(W_mu, W_u, W_d);
    lrg_main<<<N / MROWS, THREADS, smem_bytes>>>(x, b_mu, b_u, b_d);
    finalize_kernel<<<1, 1>>>((float*)d_out, N);
}